// round 1
// baseline (speedup 1.0000x reference)
#include <cuda_runtime.h>
#include <cuda_bf16.h>
#include <cstdint>

#define T_TOK 8192
#define DIM   1024
#define DFF   4096
#define NEXP  8
#define TM    128
#define TN    128
#define TK    16
#define MAX_TILES (T_TOK / TM + NEXP)   // 72 worst case

// ---------------- device scratch (allocation-free) ----------------
__device__ float g_h[(size_t)T_TOK * DFF];   // permuted hidden activations, 128 MB
__device__ int   g_perm[T_TOK];
__device__ float g_wtok[T_TOK];
__device__ int   g_eidx[T_TOK];
__device__ int   g_cnt[NEXP];
__device__ int   g_off[NEXP];
__device__ int   g_cur[NEXP];
__device__ int   g_tile_e[MAX_TILES];
__device__ int   g_tile_row[MAX_TILES];

// ---------------- kernel 0: zero counters ----------------
__global__ void zero_kernel() {
    int t = threadIdx.x;
    if (t < NEXP) { g_cnt[t] = 0; g_cur[t] = 0; }
}

// ---------------- kernel 1: router (one warp per token) ----------------
__global__ void router_kernel(const float* __restrict__ x,
                              const float* __restrict__ gw) {
    int gtid = blockIdx.x * blockDim.x + threadIdx.x;
    int tok  = gtid >> 5;
    int lane = threadIdx.x & 31;
    if (tok >= T_TOK) return;
    const float* xr = x + (size_t)tok * DIM;
    float acc[NEXP];
#pragma unroll
    for (int e = 0; e < NEXP; e++) acc[e] = 0.f;
    for (int k = lane; k < DIM; k += 32) {
        float xv = xr[k];
        const float* g = gw + k * NEXP;
#pragma unroll
        for (int e = 0; e < NEXP; e++) acc[e] += xv * g[e];
    }
#pragma unroll
    for (int e = 0; e < NEXP; e++)
#pragma unroll
        for (int o = 16; o; o >>= 1)
            acc[e] += __shfl_xor_sync(0xffffffffu, acc[e], o);
    if (lane == 0) {
        float mx = acc[0]; int ai = 0;
#pragma unroll
        for (int e = 1; e < NEXP; e++)
            if (acc[e] > mx) { mx = acc[e]; ai = e; }
        float s = 0.f;
#pragma unroll
        for (int e = 0; e < NEXP; e++) s += expf(acc[e] - mx);
        g_wtok[tok] = 1.0f / s;       // softmax prob of the argmax expert
        g_eidx[tok] = ai;
        atomicAdd(&g_cnt[ai], 1);
    }
}

// ---------------- kernel 2: offsets + tile table (1 thread) ----------------
__global__ void offsets_kernel() {
    int off = 0, t = 0;
    for (int i = 0; i < MAX_TILES; i++) g_tile_e[i] = -1;
    for (int e = 0; e < NEXP; e++) {
        g_off[e] = off;
        int c = g_cnt[e];
        for (int i = 0; i < c; i += TM) {
            g_tile_e[t]   = e;
            g_tile_row[t] = off + i;
            t++;
        }
        off += c;
    }
}

// ---------------- kernel 3: scatter tokens into permuted order ----------------
__global__ void scatter_kernel() {
    int t = blockIdx.x * blockDim.x + threadIdx.x;
    if (t >= T_TOK) return;
    int e = g_eidx[t];
    int pos = g_off[e] + atomicAdd(&g_cur[e], 1);
    g_perm[pos] = t;
}

__device__ __forceinline__ float gelu_exact(float v) {
    return 0.5f * v * (1.0f + erff(v * 0.70710678118654752f));
}

// ---------------- grouped SGEMM 1: h = gelu(x[perm] @ w1[e] + b1[e]) ----------------
__global__ __launch_bounds__(256, 2)
void gemm1_kernel(const float* __restrict__ x,
                  const float* __restrict__ w1,
                  const float* __restrict__ b1) {
    __shared__ float As[TK][TM];
    __shared__ float Bs[TK][TN];
    __shared__ const float* Arow[TM];

    int bx = blockIdx.x;
    int e  = g_tile_e[bx];
    if (e < 0) return;
    int row0 = g_tile_row[bx];
    int rend = g_off[e] + g_cnt[e];
    int nbase = blockIdx.y * TN;

    int tid = threadIdx.x;
    int tx = tid & 15, ty = tid >> 4;

    if (tid < TM) {
        int r = row0 + tid;
        Arow[tid] = (r < rend) ? (x + (size_t)g_perm[r] * DIM) : nullptr;
    }
    __syncthreads();

    const float* Bp = w1 + (size_t)e * DIM * DFF;

    float acc[8][8];
#pragma unroll
    for (int i = 0; i < 8; i++)
#pragma unroll
        for (int j = 0; j < 8; j++) acc[i][j] = 0.f;

    for (int kt = 0; kt < DIM; kt += TK) {
        // A tile (gathered rows), stored transposed As[k][m]
#pragma unroll
        for (int i = 0; i < 2; i++) {
            int idx = tid + i * 256;          // 0..511
            int m = idx >> 2;
            int kq = idx & 3;
            float4 v = make_float4(0.f, 0.f, 0.f, 0.f);
            const float* ap = Arow[m];
            if (ap) v = *(const float4*)(ap + kt + kq * 4);
            As[kq * 4 + 0][m] = v.x;
            As[kq * 4 + 1][m] = v.y;
            As[kq * 4 + 2][m] = v.z;
            As[kq * 4 + 3][m] = v.w;
        }
        // B tile, row-major [k][n]
#pragma unroll
        for (int i = 0; i < 2; i++) {
            int idx = tid + i * 256;
            int k = idx >> 5;
            int nq = idx & 31;
            *(float4*)&Bs[k][nq * 4] =
                *(const float4*)(Bp + (size_t)(kt + k) * DFF + nbase + nq * 4);
        }
        __syncthreads();
#pragma unroll
        for (int k = 0; k < TK; k++) {
            float a[8], b[8];
            *(float4*)&a[0] = *(const float4*)&As[k][ty * 8];
            *(float4*)&a[4] = *(const float4*)&As[k][ty * 8 + 4];
            *(float4*)&b[0] = *(const float4*)&Bs[k][tx * 8];
            *(float4*)&b[4] = *(const float4*)&Bs[k][tx * 8 + 4];
#pragma unroll
            for (int i = 0; i < 8; i++)
#pragma unroll
                for (int j = 0; j < 8; j++)
                    acc[i][j] += a[i] * b[j];
        }
        __syncthreads();
    }

    const float* b1e = b1 + (size_t)e * DFF;
    int nb = nbase + tx * 8;
#pragma unroll
    for (int i = 0; i < 8; i++) {
        int r = row0 + ty * 8 + i;
        if (r < rend) {
            float* hp = g_h + (size_t)r * DFF + nb;
            float o[8];
#pragma unroll
            for (int j = 0; j < 8; j++)
                o[j] = gelu_exact(acc[i][j] + b1e[nb + j]);
            *(float4*)&hp[0] = *(float4*)&o[0];
            *(float4*)&hp[4] = *(float4*)&o[4];
        }
    }
}

// ---------------- grouped SGEMM 2: out[tok] = w * (h @ w2[e] + b2[e]) ----------------
__global__ __launch_bounds__(256, 2)
void gemm2_kernel(const float* __restrict__ w2,
                  const float* __restrict__ b2,
                  float* __restrict__ out) {
    __shared__ float As[TK][TM];
    __shared__ float Bs[TK][TN];
    __shared__ const float* Arow[TM];

    int bx = blockIdx.x;
    int e  = g_tile_e[bx];
    if (e < 0) return;
    int row0 = g_tile_row[bx];
    int rend = g_off[e] + g_cnt[e];
    int nbase = blockIdx.y * TN;

    int tid = threadIdx.x;
    int tx = tid & 15, ty = tid >> 4;

    if (tid < TM) {
        int r = row0 + tid;
        Arow[tid] = (r < rend) ? (g_h + (size_t)r * DFF) : nullptr;
    }
    __syncthreads();

    const float* Bp = w2 + (size_t)e * DFF * DIM;

    float acc[8][8];
#pragma unroll
    for (int i = 0; i < 8; i++)
#pragma unroll
        for (int j = 0; j < 8; j++) acc[i][j] = 0.f;

    for (int kt = 0; kt < DFF; kt += TK) {
#pragma unroll
        for (int i = 0; i < 2; i++) {
            int idx = tid + i * 256;
            int m = idx >> 2;
            int kq = idx & 3;
            float4 v = make_float4(0.f, 0.f, 0.f, 0.f);
            const float* ap = Arow[m];
            if (ap) v = *(const float4*)(ap + kt + kq * 4);
            As[kq * 4 + 0][m] = v.x;
            As[kq * 4 + 1][m] = v.y;
            As[kq * 4 + 2][m] = v.z;
            As[kq * 4 + 3][m] = v.w;
        }
#pragma unroll
        for (int i = 0; i < 2; i++) {
            int idx = tid + i * 256;
            int k = idx >> 5;
            int nq = idx & 31;
            *(float4*)&Bs[k][nq * 4] =
                *(const float4*)(Bp + (size_t)(kt + k) * DIM + nbase + nq * 4);
        }
        __syncthreads();
#pragma unroll
        for (int k = 0; k < TK; k++) {
            float a[8], b[8];
            *(float4*)&a[0] = *(const float4*)&As[k][ty * 8];
            *(float4*)&a[4] = *(const float4*)&As[k][ty * 8 + 4];
            *(float4*)&b[0] = *(const float4*)&Bs[k][tx * 8];
            *(float4*)&b[4] = *(const float4*)&Bs[k][tx * 8 + 4];
#pragma unroll
            for (int i = 0; i < 8; i++)
#pragma unroll
                for (int j = 0; j < 8; j++)
                    acc[i][j] += a[i] * b[j];
        }
        __syncthreads();
    }

    const float* b2e = b2 + (size_t)e * DIM;
    int nb = nbase + tx * 8;
#pragma unroll
    for (int i = 0; i < 8; i++) {
        int r = row0 + ty * 8 + i;
        if (r < rend) {
            int tok = g_perm[r];
            float w = g_wtok[tok];
            float* op = out + (size_t)tok * DIM + nb;
            float o[8];
#pragma unroll
            for (int j = 0; j < 8; j++)
                o[j] = w * (acc[i][j] + b2e[nb + j]);
            *(float4*)&op[0] = *(float4*)&o[0];
            *(float4*)&op[4] = *(float4*)&o[4];
        }
    }
}

// ---------------- launch ----------------
extern "C" void kernel_launch(void* const* d_in, const int* in_sizes, int n_in,
                              void* d_out, int out_size) {
    const float* x      = (const float*)d_in[0];   // [4,2048,1024]
    const float* gate_w = (const float*)d_in[1];   // [1024,8]
    const float* w1     = (const float*)d_in[2];   // [8,1024,4096]
    const float* b1     = (const float*)d_in[3];   // [8,4096]
    const float* w2     = (const float*)d_in[4];   // [8,4096,1024]
    const float* b2     = (const float*)d_in[5];   // [8,1024]
    float* out = (float*)d_out;

    zero_kernel<<<1, 32>>>();
    router_kernel<<<T_TOK / 8, 256>>>(x, gate_w);   // 8 warps/block, 1 warp/token
    offsets_kernel<<<1, 1>>>();
    scatter_kernel<<<T_TOK / 256, 256>>>();
    gemm1_kernel<<<dim3(MAX_TILES, DFF / TN), 256>>>(x, w1, b1);
    gemm2_kernel<<<dim3(MAX_TILES, DIM / TN), 256>>>(w2, b2, out);
}

// round 3
// speedup vs baseline: 2.1501x; 2.1501x over previous
#include <cuda_runtime.h>
#include <cuda_bf16.h>
#include <cstdint>

#define T_TOK 8192
#define DIM   1024
#define DFF   4096
#define NEXP  8
#define TM    128
#define MAX_TILES (T_TOK / TM + NEXP)   // 72

// ======================= device scratch =======================
__device__ __nv_bfloat16 g_xhi[(size_t)T_TOK * DIM];
__device__ __nv_bfloat16 g_xlo[(size_t)T_TOK * DIM];
__device__ __nv_bfloat16 g_w1hi[(size_t)NEXP * DFF * DIM];   // [e][n][k]
__device__ __nv_bfloat16 g_w1lo[(size_t)NEXP * DFF * DIM];
__device__ __nv_bfloat16 g_w2hi[(size_t)NEXP * DIM * DFF];   // [e][n][k]
__device__ __nv_bfloat16 g_w2lo[(size_t)NEXP * DIM * DFF];
__device__ __nv_bfloat16 g_hhi[(size_t)T_TOK * DFF];
__device__ __nv_bfloat16 g_hlo[(size_t)T_TOK * DFF];
__device__ int   g_perm[T_TOK];
__device__ float g_wtok[T_TOK];
__device__ int   g_eidx[T_TOK];
__device__ int   g_cnt[NEXP], g_off[NEXP], g_cur[NEXP];
__device__ int   g_tile_e[MAX_TILES], g_tile_row[MAX_TILES];

// ======================= small kernels =======================
__global__ void zero_kernel() {
    int t = threadIdx.x;
    if (t < NEXP) { g_cnt[t] = 0; g_cur[t] = 0; }
}

__global__ void router_kernel(const float* __restrict__ x, const float* __restrict__ gw) {
    int gtid = blockIdx.x * blockDim.x + threadIdx.x;
    int tok = gtid >> 5, lane = threadIdx.x & 31;
    if (tok >= T_TOK) return;
    const float* xr = x + (size_t)tok * DIM;
    float acc[NEXP];
#pragma unroll
    for (int e = 0; e < NEXP; e++) acc[e] = 0.f;
    for (int k = lane; k < DIM; k += 32) {
        float xv = xr[k];
        const float* g = gw + k * NEXP;
#pragma unroll
        for (int e = 0; e < NEXP; e++) acc[e] += xv * g[e];
    }
#pragma unroll
    for (int e = 0; e < NEXP; e++)
#pragma unroll
        for (int o = 16; o; o >>= 1) acc[e] += __shfl_xor_sync(0xffffffffu, acc[e], o);
    if (lane == 0) {
        float mx = acc[0]; int ai = 0;
#pragma unroll
        for (int e = 1; e < NEXP; e++) if (acc[e] > mx) { mx = acc[e]; ai = e; }
        float s = 0.f;
#pragma unroll
        for (int e = 0; e < NEXP; e++) s += expf(acc[e] - mx);
        g_wtok[tok] = 1.0f / s;
        g_eidx[tok] = ai;
        atomicAdd(&g_cnt[ai], 1);
    }
}

__global__ void offsets_kernel() {
    int off = 0, t = 0;
    for (int i = 0; i < MAX_TILES; i++) g_tile_e[i] = -1;
    for (int e = 0; e < NEXP; e++) {
        g_off[e] = off;
        int c = g_cnt[e];
        for (int i = 0; i < c; i += TM) { g_tile_e[t] = e; g_tile_row[t] = off + i; t++; }
        off += c;
    }
}

__global__ void scatter_kernel() {
    int t = blockIdx.x * blockDim.x + threadIdx.x;
    if (t >= T_TOK) return;
    int e = g_eidx[t];
    g_perm[g_off[e] + atomicAdd(&g_cur[e], 1)] = t;
}

__global__ void convx_kernel(const float* __restrict__ x) {
    int i = blockIdx.x * 256 + threadIdx.x;
    if (i >= T_TOK * DIM / 4) return;
    float4 v = ((const float4*)x)[i];
    float f[4] = {v.x, v.y, v.z, v.w};
    __nv_bfloat162* hp = (__nv_bfloat162*)g_xhi + i * 2;
    __nv_bfloat162* lp = (__nv_bfloat162*)g_xlo + i * 2;
    __nv_bfloat16 h[4]; __nv_bfloat16 l[4];
#pragma unroll
    for (int t = 0; t < 4; t++) {
        h[t] = __float2bfloat16(f[t]);
        l[t] = __float2bfloat16(f[t] - __bfloat162float(h[t]));
    }
    hp[0] = __halves2bfloat162(h[0], h[1]); hp[1] = __halves2bfloat162(h[2], h[3]);
    lp[0] = __halves2bfloat162(l[0], l[1]); lp[1] = __halves2bfloat162(l[2], l[3]);
}

template<int WSEL>
__global__ void transconv_kernel(const float* __restrict__ W) {
    constexpr int K = (WSEL == 1) ? DIM : DFF;
    constexpr int N = (WSEL == 1) ? DFF : DIM;
    __nv_bfloat16* hi = (WSEL == 1) ? g_w1hi : g_w2hi;
    __nv_bfloat16* lo = (WSEL == 1) ? g_w1lo : g_w2lo;
    __shared__ float t[32][33];
    int e = blockIdx.z;
    int n0 = blockIdx.x * 32, k0 = blockIdx.y * 32;
    const float* We = W + (size_t)e * K * N;
    int tx = threadIdx.x, ty = threadIdx.y;
#pragma unroll
    for (int i = 0; i < 4; i++)
        t[ty + i * 8][tx] = We[(size_t)(k0 + ty + i * 8) * N + n0 + tx];
    __syncthreads();
    size_t ob = (size_t)e * N * K;
#pragma unroll
    for (int i = 0; i < 4; i++) {
        float v = t[tx][ty + i * 8];
        __nv_bfloat16 h = __float2bfloat16(v);
        float rv = v - __bfloat162float(h);
        size_t o = ob + (size_t)(n0 + ty + i * 8) * K + (k0 + tx);
        hi[o] = h; lo[o] = __float2bfloat16(rv);
    }
}

// ======================= HMMA grouped GEMM =======================
// CTA 128x128, KC=32, 8 warps (4m x 2n), warp tile 32x64.
// SMEM per stage: Ahi(10240) Alo(10240) Bhi(10240) Blo(10240) = 40960.
// Rows: 32 bf16 + 8 pad = 40 halves = 80B stride (conflict-free ldmatrix).
#define KC       32
#define RSTRIDE  80
#define HALF_T   10240
#define STAGE_B  40960
#define SM_AROWH 81920
#define SM_AROWL 82944
#define SMEM_BYTES 83968

__device__ __forceinline__ uint32_t smem_u32(const void* p) {
    uint32_t a;
    asm("{ .reg .u64 t; cvta.to.shared.u64 t, %1; cvt.u32.u64 %0, t; }" : "=r"(a) : "l"(p));
    return a;
}
__device__ __forceinline__ void cp16(uint32_t d, const void* s) {
    asm volatile("cp.async.cg.shared.global [%0], [%1], 16;"
        :: "r"(d), "l"(__cvta_generic_to_global(s)) : "memory");
}
__device__ __forceinline__ void ldm4(uint32_t* r, uint32_t a) {
    asm volatile("ldmatrix.sync.aligned.m8n8.x4.shared.b16 {%0,%1,%2,%3}, [%4];"
        : "=r"(r[0]), "=r"(r[1]), "=r"(r[2]), "=r"(r[3]) : "r"(a));
}
__device__ __forceinline__ void mma_bf16(float* c, const uint32_t* a, const uint32_t* b) {
    asm volatile("mma.sync.aligned.m16n8k16.row.col.f32.bf16.bf16.f32 "
        "{%0,%1,%2,%3}, {%4,%5,%6,%7}, {%8,%9}, {%0,%1,%2,%3};"
        : "+f"(c[0]), "+f"(c[1]), "+f"(c[2]), "+f"(c[3])
        : "r"(a[0]), "r"(a[1]), "r"(a[2]), "r"(a[3]), "r"(b[0]), "r"(b[1]));
}
__device__ __forceinline__ float gelu_exact(float v) {
    return 0.5f * v * (1.0f + erff(v * 0.70710678118654752f));
}

template<int MODE>  // 0: x->h, 1: h->out
__global__ __launch_bounds__(256, 1) void gemm_tc(const float* __restrict__ bias,
                                                  float* __restrict__ outp) {
    constexpr int KTOT = (MODE == 0) ? DIM : DFF;
    constexpr int NTOT = (MODE == 0) ? DFF : DIM;
    constexpr int NC = KTOT / KC;

    extern __shared__ __align__(128) char smem[];
    int by = blockIdx.y;
    int e = g_tile_e[by];
    if (e < 0) return;
    int row0 = g_tile_row[by];
    int rend = g_off[e] + g_cnt[e];
    int nbase = blockIdx.x * 128;

    uint32_t sb = smem_u32(smem);
    int tid = threadIdx.x, wid = tid >> 5, lane = tid & 31;

    const __nv_bfloat16* Ahi = (MODE == 0) ? g_xhi : g_hhi;
    const __nv_bfloat16* Alo = (MODE == 0) ? g_xlo : g_hlo;
    const __nv_bfloat16* BeH = ((MODE == 0) ? g_w1hi : g_w2hi) + ((size_t)e * NTOT + nbase) * KTOT;
    const __nv_bfloat16* BeL = ((MODE == 0) ? g_w1lo : g_w2lo) + ((size_t)e * NTOT + nbase) * KTOT;

    const __nv_bfloat16** ArH = (const __nv_bfloat16**)(smem + SM_AROWH);
    const __nv_bfloat16** ArL = (const __nv_bfloat16**)(smem + SM_AROWL);
    if (tid < 128) {
        int r = row0 + tid;
        int rc = (r < rend) ? r : (rend - 1);
        int src = (MODE == 0) ? g_perm[rc] : rc;
        ArH[tid] = Ahi + (size_t)src * KTOT;
        ArL[tid] = Alo + (size_t)src * KTOT;
    }
    __syncthreads();

    // per-thread load indices
    int lrow = (tid >> 1) & 127;         // not used; kept simple below
    (void)lrow;

    float acc[2][8][4];
#pragma unroll
    for (int i = 0; i < 2; i++)
#pragma unroll
        for (int j = 0; j < 8; j++)
#pragma unroll
            for (int q = 0; q < 4; q++) acc[i][j][q] = 0.f;

    int mw = wid & 3, nw = wid >> 2;
    uint32_t aoff = (uint32_t)((lane & 15) * RSTRIDE + (lane >> 4) * 16);
    uint32_t boff = (uint32_t)(((lane & 7) + ((lane >> 4) & 1) * 8) * RSTRIDE + ((lane >> 3) & 1) * 16);

    auto issue = [&](int p, int kt) {
        uint32_t base = sb + p * STAGE_B;
#pragma unroll
        for (int i = 0; i < 4; i++) {
            int idx = tid + i * 256;
            int row = (idx >> 2) & 127, c = idx & 3, half = idx >> 9;
            const __nv_bfloat16* s = (half ? ArL[row] : ArH[row]) + kt + c * 8;
            cp16(base + half * HALF_T + row * RSTRIDE + c * 16, s);
        }
#pragma unroll
        for (int i = 0; i < 4; i++) {
            int idx = tid + i * 256;
            int row = (idx >> 2) & 127, c = idx & 3, half = idx >> 9;
            const __nv_bfloat16* s = (half ? BeL : BeH) + (size_t)row * KTOT + kt + c * 8;
            cp16(base + 20480 + half * HALF_T + row * RSTRIDE + c * 16, s);
        }
        asm volatile("cp.async.commit_group;" ::: "memory");
    };

    issue(0, 0);

    for (int kc = 0; kc < NC; kc++) {
        int p = kc & 1;
        if (kc + 1 < NC) {
            issue(p ^ 1, (kc + 1) * KC);
            asm volatile("cp.async.wait_group 1;" ::: "memory");
        } else {
            asm volatile("cp.async.wait_group 0;" ::: "memory");
        }
        __syncthreads();

        uint32_t ab = sb + p * STAGE_B;
        uint32_t bb = ab + 20480;
#pragma unroll
        for (int ks = 0; ks < 2; ks++) {
            uint32_t kb = ks * 32;   // 16 halves * 2B
            uint32_t a0 = ab + (uint32_t)(mw * 32) * RSTRIDE + kb + aoff;
            uint32_t ah[2][4], al[2][4];
            ldm4(ah[0], a0);
            ldm4(ah[1], a0 + 16 * RSTRIDE);
            ldm4(al[0], a0 + HALF_T);
            ldm4(al[1], a0 + HALF_T + 16 * RSTRIDE);
            uint32_t bh[8][2], bl[8][2];
#pragma unroll
            for (int jj = 0; jj < 4; jj++) {
                uint32_t b0 = bb + (uint32_t)(nw * 64 + jj * 16) * RSTRIDE + kb + boff;
                uint32_t t[4];
                ldm4(t, b0);
                bh[2 * jj][0] = t[0]; bh[2 * jj][1] = t[1];
                bh[2 * jj + 1][0] = t[2]; bh[2 * jj + 1][1] = t[3];
                ldm4(t, b0 + HALF_T);
                bl[2 * jj][0] = t[0]; bl[2 * jj][1] = t[1];
                bl[2 * jj + 1][0] = t[2]; bl[2 * jj + 1][1] = t[3];
            }
#pragma unroll
            for (int i = 0; i < 2; i++)
#pragma unroll
                for (int j = 0; j < 8; j++) {
                    mma_bf16(acc[i][j], ah[i], bh[j]);
                    mma_bf16(acc[i][j], ah[i], bl[j]);
                    mma_bf16(acc[i][j], al[i], bh[j]);
                }
        }
        __syncthreads();
    }

    // ---------------- epilogue ----------------
    int rbase = row0 + mw * 32;
#pragma unroll
    for (int i = 0; i < 2; i++) {
        int r1 = rbase + i * 16 + (lane >> 2);
        int r2 = r1 + 8;
        bool ok1 = r1 < rend, ok2 = r2 < rend;
        int tok1 = 0, tok2 = 0; float wg1 = 0.f, wg2 = 0.f;
        if (MODE == 1) {
            if (ok1) { tok1 = g_perm[r1]; wg1 = g_wtok[tok1]; }
            if (ok2) { tok2 = g_perm[r2]; wg2 = g_wtok[tok2]; }
        }
#pragma unroll
        for (int j = 0; j < 8; j++) {
            int n = nbase + nw * 64 + j * 8 + (lane & 3) * 2;
            float2 bv = *(const float2*)(bias + (size_t)e * NTOT + n);
            if (MODE == 0) {
                if (ok1) {
                    float v0 = gelu_exact(acc[i][j][0] + bv.x);
                    float v1 = gelu_exact(acc[i][j][1] + bv.y);
                    __nv_bfloat16 h0 = __float2bfloat16(v0), h1 = __float2bfloat16(v1);
                    __nv_bfloat16 l0 = __float2bfloat16(v0 - __bfloat162float(h0));
                    __nv_bfloat16 l1 = __float2bfloat16(v1 - __bfloat162float(h1));
                    *(__nv_bfloat162*)(g_hhi + (size_t)r1 * DFF + n) = __halves2bfloat162(h0, h1);
                    *(__nv_bfloat162*)(g_hlo + (size_t)r1 * DFF + n) = __halves2bfloat162(l0, l1);
                }
                if (ok2) {
                    float v0 = gelu_exact(acc[i][j][2] + bv.x);
                    float v1 = gelu_exact(acc[i][j][3] + bv.y);
                    __nv_bfloat16 h0 = __float2bfloat16(v0), h1 = __float2bfloat16(v1);
                    __nv_bfloat16 l0 = __float2bfloat16(v0 - __bfloat162float(h0));
                    __nv_bfloat16 l1 = __float2bfloat16(v1 - __bfloat162float(h1));
                    *(__nv_bfloat162*)(g_hhi + (size_t)r2 * DFF + n) = __halves2bfloat162(h0, h1);
                    *(__nv_bfloat162*)(g_hlo + (size_t)r2 * DFF + n) = __halves2bfloat162(l0, l1);
                }
            } else {
                if (ok1) {
                    float2 ov;
                    ov.x = wg1 * (acc[i][j][0] + bv.x);
                    ov.y = wg1 * (acc[i][j][1] + bv.y);
                    *(float2*)(outp + (size_t)tok1 * DIM + n) = ov;
                }
                if (ok2) {
                    float2 ov;
                    ov.x = wg2 * (acc[i][j][2] + bv.x);
                    ov.y = wg2 * (acc[i][j][3] + bv.y);
                    *(float2*)(outp + (size_t)tok2 * DIM + n) = ov;
                }
            }
        }
    }
}

// ======================= launch =======================
extern "C" void kernel_launch(void* const* d_in, const int* in_sizes, int n_in,
                              void* d_out, int out_size) {
    const float* x      = (const float*)d_in[0];
    const float* gate_w = (const float*)d_in[1];
    const float* w1     = (const float*)d_in[2];
    const float* b1     = (const float*)d_in[3];
    const float* w2     = (const float*)d_in[4];
    const float* b2     = (const float*)d_in[5];
    float* out = (float*)d_out;

    cudaFuncSetAttribute(gemm_tc<0>, cudaFuncAttributeMaxDynamicSharedMemorySize, SMEM_BYTES);
    cudaFuncSetAttribute(gemm_tc<1>, cudaFuncAttributeMaxDynamicSharedMemorySize, SMEM_BYTES);

    zero_kernel<<<1, 32>>>();
    router_kernel<<<T_TOK / 8, 256>>>(x, gate_w);
    offsets_kernel<<<1, 1>>>();
    scatter_kernel<<<T_TOK / 256, 256>>>();

    convx_kernel<<<(T_TOK * DIM / 4 + 255) / 256, 256>>>(x);
    transconv_kernel<1><<<dim3(DFF / 32, DIM / 32, NEXP), dim3(32, 8)>>>(w1);
    transconv_kernel<2><<<dim3(DIM / 32, DFF / 32, NEXP), dim3(32, 8)>>>(w2);

    gemm_tc<0><<<dim3(DFF / 128, MAX_TILES), 256, SMEM_BYTES>>>(b1, nullptr);
    gemm_tc<1><<<dim3(DIM / 128, MAX_TILES), 256, SMEM_BYTES>>>(b2, out);
}

// round 5
// speedup vs baseline: 2.5111x; 1.1679x over previous
#include <cuda_runtime.h>
#include <cuda_bf16.h>
#include <cstdint>

#define T_TOK 8192
#define DIM   1024
#define DFF   4096
#define NEXP  8
#define TM    128
#define MAX_TILES (T_TOK / TM + NEXP)   // 72
#define GEMM_GRID 296

// ======================= device scratch =======================
__device__ __nv_bfloat16 g_xhi[(size_t)T_TOK * DIM];
__device__ __nv_bfloat16 g_xlo[(size_t)T_TOK * DIM];
__device__ __nv_bfloat16 g_w1hi[(size_t)NEXP * DFF * DIM];   // [e][n][k]
__device__ __nv_bfloat16 g_w1lo[(size_t)NEXP * DFF * DIM];
__device__ __nv_bfloat16 g_w2hi[(size_t)NEXP * DIM * DFF];   // [e][n][k]
__device__ __nv_bfloat16 g_w2lo[(size_t)NEXP * DIM * DFF];
__device__ __nv_bfloat16 g_hhi[(size_t)T_TOK * DFF];
__device__ __nv_bfloat16 g_hlo[(size_t)T_TOK * DFF];
__device__ int   g_perm[T_TOK];
__device__ float g_wtok[T_TOK];
__device__ int   g_eidx[T_TOK];
__device__ int   g_cnt[NEXP], g_off[NEXP], g_cur[NEXP];
__device__ int   g_tile_e[MAX_TILES], g_tile_row[MAX_TILES];
__device__ int   g_ntile;

// ======================= small kernels =======================
__global__ void zero_kernel() {
    int t = threadIdx.x;
    if (t < NEXP) { g_cnt[t] = 0; g_cur[t] = 0; }
}

__global__ void router_kernel(const float* __restrict__ x, const float* __restrict__ gw) {
    int gtid = blockIdx.x * blockDim.x + threadIdx.x;
    int tok = gtid >> 5, lane = threadIdx.x & 31;
    if (tok >= T_TOK) return;
    const float* xr = x + (size_t)tok * DIM;
    float acc[NEXP];
#pragma unroll
    for (int e = 0; e < NEXP; e++) acc[e] = 0.f;
    for (int k = lane; k < DIM; k += 32) {
        float xv = xr[k];
        const float* g = gw + k * NEXP;
#pragma unroll
        for (int e = 0; e < NEXP; e++) acc[e] += xv * g[e];
    }
#pragma unroll
    for (int e = 0; e < NEXP; e++)
#pragma unroll
        for (int o = 16; o; o >>= 1) acc[e] += __shfl_xor_sync(0xffffffffu, acc[e], o);
    if (lane == 0) {
        float mx = acc[0]; int ai = 0;
#pragma unroll
        for (int e = 1; e < NEXP; e++) if (acc[e] > mx) { mx = acc[e]; ai = e; }
        float s = 0.f;
#pragma unroll
        for (int e = 0; e < NEXP; e++) s += expf(acc[e] - mx);
        g_wtok[tok] = 1.0f / s;
        g_eidx[tok] = ai;
        atomicAdd(&g_cnt[ai], 1);
    }
}

__global__ void offsets_kernel() {
    int off = 0, t = 0;
    for (int i = 0; i < MAX_TILES; i++) g_tile_e[i] = -1;
    for (int e = 0; e < NEXP; e++) {
        g_off[e] = off;
        int c = g_cnt[e];
        for (int i = 0; i < c; i += TM) { g_tile_e[t] = e; g_tile_row[t] = off + i; t++; }
        off += c;
    }
    g_ntile = t;
}

__global__ void scatter_kernel() {
    int t = blockIdx.x * blockDim.x + threadIdx.x;
    if (t >= T_TOK) return;
    int e = g_eidx[t];
    g_perm[g_off[e] + atomicAdd(&g_cur[e], 1)] = t;
}

__global__ void convx_kernel(const float* __restrict__ x) {
    int i = blockIdx.x * 256 + threadIdx.x;
    if (i >= T_TOK * DIM / 4) return;
    float4 v = ((const float4*)x)[i];
    float f[4] = {v.x, v.y, v.z, v.w};
    __nv_bfloat162* hp = (__nv_bfloat162*)g_xhi + i * 2;
    __nv_bfloat162* lp = (__nv_bfloat162*)g_xlo + i * 2;
    __nv_bfloat16 h[4]; __nv_bfloat16 l[4];
#pragma unroll
    for (int t = 0; t < 4; t++) {
        h[t] = __float2bfloat16(f[t]);
        l[t] = __float2bfloat16(f[t] - __bfloat162float(h[t]));
    }
    hp[0] = __halves2bfloat162(h[0], h[1]); hp[1] = __halves2bfloat162(h[2], h[3]);
    lp[0] = __halves2bfloat162(l[0], l[1]); lp[1] = __halves2bfloat162(l[2], l[3]);
}

template<int WSEL>
__global__ void transconv_kernel(const float* __restrict__ W) {
    constexpr int K = (WSEL == 1) ? DIM : DFF;
    constexpr int N = (WSEL == 1) ? DFF : DIM;
    __nv_bfloat16* hi = (WSEL == 1) ? g_w1hi : g_w2hi;
    __nv_bfloat16* lo = (WSEL == 1) ? g_w1lo : g_w2lo;
    __shared__ float t[32][33];
    int e = blockIdx.z;
    int n0 = blockIdx.x * 32, k0 = blockIdx.y * 32;
    const float* We = W + (size_t)e * K * N;
    int tx = threadIdx.x, ty = threadIdx.y;
#pragma unroll
    for (int i = 0; i < 4; i++)
        t[ty + i * 8][tx] = We[(size_t)(k0 + ty + i * 8) * N + n0 + tx];
    __syncthreads();
    size_t ob = (size_t)e * N * K;
#pragma unroll
    for (int i = 0; i < 4; i++) {
        float v = t[tx][ty + i * 8];
        __nv_bfloat16 h = __float2bfloat16(v);
        float rv = v - __bfloat162float(h);
        size_t o = ob + (size_t)(n0 + ty + i * 8) * K + (k0 + tx);
        hi[o] = h; lo[o] = __float2bfloat16(rv);
    }
}

// ======================= HMMA grouped GEMM (persistent) =======================
#define KC       32
#define RSTRIDE  80
#define HALF_T   10240
#define STAGE_B  40960
#define SM_AROW  81920                    // 128 x 8B pointers (hi only)
#define SMEM_BYTES 82944

__device__ __forceinline__ uint32_t smem_u32(const void* p) {
    uint32_t a;
    asm("{ .reg .u64 t; cvta.to.shared.u64 t, %1; cvt.u32.u64 %0, t; }" : "=r"(a) : "l"(p));
    return a;
}
__device__ __forceinline__ void cp16(uint32_t d, const void* s) {
    asm volatile("cp.async.cg.shared.global [%0], [%1], 16;"
        :: "r"(d), "l"(__cvta_generic_to_global(s)) : "memory");
}
__device__ __forceinline__ void ldm4(uint32_t* r, uint32_t a) {
    asm volatile("ldmatrix.sync.aligned.m8n8.x4.shared.b16 {%0,%1,%2,%3}, [%4];"
        : "=r"(r[0]), "=r"(r[1]), "=r"(r[2]), "=r"(r[3]) : "r"(a));
}
__device__ __forceinline__ void mma_bf16(float* c, const uint32_t* a, const uint32_t* b) {
    asm volatile("mma.sync.aligned.m16n8k16.row.col.f32.bf16.bf16.f32 "
        "{%0,%1,%2,%3}, {%4,%5,%6,%7}, {%8,%9}, {%0,%1,%2,%3};"
        : "+f"(c[0]), "+f"(c[1]), "+f"(c[2]), "+f"(c[3])
        : "r"(a[0]), "r"(a[1]), "r"(a[2]), "r"(a[3]), "r"(b[0]), "r"(b[1]));
}
__device__ __forceinline__ float gelu_exact(float v) {
    return 0.5f * v * (1.0f + erff(v * 0.70710678118654752f));
}

template<int MODE>  // 0: x->h, 1: h->out
__global__ __launch_bounds__(256, 2) void gemm_tc(const float* __restrict__ bias,
                                                  float* __restrict__ outp) {
    constexpr int KTOT = (MODE == 0) ? DIM : DFF;
    constexpr int NTOT = (MODE == 0) ? DFF : DIM;
    constexpr int NC = KTOT / KC;
    constexpr int NT = NTOT / 128;

    extern __shared__ __align__(128) char smem[];
    uint32_t sb = smem_u32(smem);
    int tid = threadIdx.x, wid = tid >> 5, lane = tid & 31;
    int mw = wid & 3, nw = wid >> 2;

    const __nv_bfloat16* Ahi = (MODE == 0) ? g_xhi : g_hhi;
    const ptrdiff_t dAlo = (MODE == 0) ? (g_xlo - g_xhi) : (g_hlo - g_hhi);
    const __nv_bfloat16* WH = (MODE == 0) ? g_w1hi : g_w2hi;
    const ptrdiff_t dBlo = (MODE == 0) ? (g_w1lo - g_w1hi) : (g_w2lo - g_w2hi);

    const __nv_bfloat16** ArH = (const __nv_bfloat16**)(smem + SM_AROW);

    uint32_t aoff = (uint32_t)((lane & 15) * RSTRIDE + (lane >> 4) * 16);
    uint32_t boff = (uint32_t)(((lane & 7) + ((lane >> 4) & 1) * 8) * RSTRIDE + ((lane >> 3) & 1) * 16);

    int nitems = g_ntile * NT;

    for (int item = blockIdx.x; item < nitems; item += GEMM_GRID) {
        int ti = item / NT;
        int nbase = (item - ti * NT) * 128;
        int e = g_tile_e[ti];
        int row0 = g_tile_row[ti];
        int rend = g_off[e] + g_cnt[e];

        __syncthreads();            // protect ArH from previous item's loads
        if (tid < 128) {
            int r = row0 + tid;
            int rc = (r < rend) ? r : (rend - 1);
            int src = (MODE == 0) ? g_perm[rc] : rc;
            ArH[tid] = Ahi + (size_t)src * KTOT;
        }
        __syncthreads();

        const __nv_bfloat16* BeH = WH + ((size_t)e * NTOT + nbase) * KTOT;

        float acc[2][8][4];
#pragma unroll
        for (int i = 0; i < 2; i++)
#pragma unroll
            for (int j = 0; j < 8; j++)
#pragma unroll
                for (int q = 0; q < 4; q++) acc[i][j][q] = 0.f;

        // ---- async copy of one K-chunk into stage p ----
        auto issue = [&](int p, int kt) {
            uint32_t base = sb + p * STAGE_B;
#pragma unroll
            for (int i = 0; i < 4; i++) {
                int idx = tid + i * 256;
                int row = (idx >> 2) & 127, c = idx & 3, half = idx >> 9;
                const __nv_bfloat16* s = ArH[row] + (half ? dAlo : 0) + kt + c * 8;
                cp16(base + half * HALF_T + row * RSTRIDE + c * 16, s);
            }
#pragma unroll
            for (int i = 0; i < 4; i++) {
                int idx = tid + i * 256;
                int row = (idx >> 2) & 127, c = idx & 3, half = idx >> 9;
                const __nv_bfloat16* s = BeH + (half ? dBlo : 0) + (size_t)row * KTOT + kt + c * 8;
                cp16(base + 20480 + half * HALF_T + row * RSTRIDE + c * 16, s);
            }
            asm volatile("cp.async.commit_group;" ::: "memory");
        };

        issue(0, 0);

        for (int kc = 0; kc < NC; kc++) {
            int p = kc & 1;
            if (kc + 1 < NC) {
                issue(p ^ 1, (kc + 1) * KC);
                asm volatile("cp.async.wait_group 1;" ::: "memory");
            } else {
                asm volatile("cp.async.wait_group 0;" ::: "memory");
            }
            __syncthreads();

            uint32_t ab = sb + p * STAGE_B;
            uint32_t bb = ab + 20480;
#pragma unroll
            for (int ks = 0; ks < 2; ks++) {
                uint32_t kb = ks * 32;
                uint32_t a0 = ab + (uint32_t)(mw * 32) * RSTRIDE + kb + aoff;
                uint32_t ah[2][4], al[2][4];
                ldm4(ah[0], a0);
                ldm4(ah[1], a0 + 16 * RSTRIDE);
                ldm4(al[0], a0 + HALF_T);
                ldm4(al[1], a0 + HALF_T + 16 * RSTRIDE);
#pragma unroll
                for (int jj = 0; jj < 4; jj++) {
                    uint32_t b0 = bb + (uint32_t)(nw * 64 + jj * 16) * RSTRIDE + kb + boff;
                    uint32_t bh[4], bl[4];
                    ldm4(bh, b0);
                    ldm4(bl, b0 + HALF_T);
#pragma unroll
                    for (int i = 0; i < 2; i++) {
                        mma_bf16(acc[i][2 * jj],     ah[i], bh);
                        mma_bf16(acc[i][2 * jj],     al[i], bh);
                        mma_bf16(acc[i][2 * jj],     ah[i], bl);
                        mma_bf16(acc[i][2 * jj + 1], ah[i], bh + 2);
                        mma_bf16(acc[i][2 * jj + 1], al[i], bh + 2);
                        mma_bf16(acc[i][2 * jj + 1], ah[i], bl + 2);
                    }
                }
            }
            __syncthreads();
        }

        // ---------------- epilogue ----------------
        int rbase = row0 + mw * 32;
#pragma unroll
        for (int i = 0; i < 2; i++) {
            int r1 = rbase + i * 16 + (lane >> 2);
            int r2 = r1 + 8;
            bool ok1 = r1 < rend, ok2 = r2 < rend;
            int tok1 = 0, tok2 = 0; float wg1 = 0.f, wg2 = 0.f;
            if (MODE == 1) {
                if (ok1) { tok1 = g_perm[r1]; wg1 = g_wtok[tok1]; }
                if (ok2) { tok2 = g_perm[r2]; wg2 = g_wtok[tok2]; }
            }
#pragma unroll
            for (int j = 0; j < 8; j++) {
                int n = nbase + nw * 64 + j * 8 + (lane & 3) * 2;
                float2 bv = *(const float2*)(bias + (size_t)e * NTOT + n);
                if (MODE == 0) {
                    if (ok1) {
                        float v0 = gelu_exact(acc[i][j][0] + bv.x);
                        float v1 = gelu_exact(acc[i][j][1] + bv.y);
                        __nv_bfloat16 h0 = __float2bfloat16(v0), h1 = __float2bfloat16(v1);
                        __nv_bfloat16 l0 = __float2bfloat16(v0 - __bfloat162float(h0));
                        __nv_bfloat16 l1 = __float2bfloat16(v1 - __bfloat162float(h1));
                        *(__nv_bfloat162*)(g_hhi + (size_t)r1 * DFF + n) = __halves2bfloat162(h0, h1);
                        *(__nv_bfloat162*)(g_hlo + (size_t)r1 * DFF + n) = __halves2bfloat162(l0, l1);
                    }
                    if (ok2) {
                        float v0 = gelu_exact(acc[i][j][2] + bv.x);
                        float v1 = gelu_exact(acc[i][j][3] + bv.y);
                        __nv_bfloat16 h0 = __float2bfloat16(v0), h1 = __float2bfloat16(v1);
                        __nv_bfloat16 l0 = __float2bfloat16(v0 - __bfloat162float(h0));
                        __nv_bfloat16 l1 = __float2bfloat16(v1 - __bfloat162float(h1));
                        *(__nv_bfloat162*)(g_hhi + (size_t)r2 * DFF + n) = __halves2bfloat162(h0, h1);
                        *(__nv_bfloat162*)(g_hlo + (size_t)r2 * DFF + n) = __halves2bfloat162(l0, l1);
                    }
                } else {
                    if (ok1) {
                        float2 ov;
                        ov.x = wg1 * (acc[i][j][0] + bv.x);
                        ov.y = wg1 * (acc[i][j][1] + bv.y);
                        *(float2*)(outp + (size_t)tok1 * DIM + n) = ov;
                    }
                    if (ok2) {
                        float2 ov;
                        ov.x = wg2 * (acc[i][j][2] + bv.x);
                        ov.y = wg2 * (acc[i][j][3] + bv.y);
                        *(float2*)(outp + (size_t)tok2 * DIM + n) = ov;
                    }
                }
            }
        }
    }
}

// ======================= launch =======================
extern "C" void kernel_launch(void* const* d_in, const int* in_sizes, int n_in,
                              void* d_out, int out_size) {
    const float* x      = (const float*)d_in[0];
    const float* gate_w = (const float*)d_in[1];
    const float* w1     = (const float*)d_in[2];
    const float* b1     = (const float*)d_in[3];
    const float* w2     = (const float*)d_in[4];
    const float* b2     = (const float*)d_in[5];
    float* out = (float*)d_out;

    cudaFuncSetAttribute(gemm_tc<0>, cudaFuncAttributeMaxDynamicSharedMemorySize, SMEM_BYTES);
    cudaFuncSetAttribute(gemm_tc<1>, cudaFuncAttributeMaxDynamicSharedMemorySize, SMEM_BYTES);

    zero_kernel<<<1, 32>>>();
    router_kernel<<<T_TOK / 8, 256>>>(x, gate_w);
    offsets_kernel<<<1, 1>>>();
    scatter_kernel<<<T_TOK / 256, 256>>>();

    convx_kernel<<<(T_TOK * DIM / 4 + 255) / 256, 256>>>(x);
    transconv_kernel<1><<<dim3(DFF / 32, DIM / 32, NEXP), dim3(32, 8)>>>(w1);
    transconv_kernel<2><<<dim3(DIM / 32, DFF / 32, NEXP), dim3(32, 8)>>>(w2);

    gemm_tc<0><<<GEMM_GRID, 256, SMEM_BYTES>>>(b1, nullptr);
    gemm_tc<1><<<GEMM_GRID, 256, SMEM_BYTES>>>(b2, out);
}